// round 2
// baseline (speedup 1.0000x reference)
#include <cuda_runtime.h>
#include <cuda_bf16.h>
#include <cuda_fp8.h>
#include <cstdint>

#define M_DIM 4096
#define H_DIM 4096
#define I_DIM 14336
#define KB_H (H_DIM/128)
#define KB_I (I_DIM/128)

// ---- static scratch ----
__device__ int g_fmt;
__device__ __nv_bfloat16 g_wg[(size_t)I_DIM*H_DIM];
__device__ __nv_bfloat16 g_wu[(size_t)I_DIM*H_DIM];
__device__ __nv_bfloat16 g_wd[(size_t)H_DIM*I_DIM];
__device__ __nv_bfloat16 g_xq[(size_t)M_DIM*H_DIM];
__device__ float         g_xs[(size_t)M_DIM*KB_H];
__device__ float         g_gate[(size_t)M_DIM*I_DIM];
__device__ float         g_up[(size_t)M_DIM*I_DIM];
__device__ __nv_bfloat16 g_hq[(size_t)M_DIM*I_DIM];
__device__ float         g_hs[(size_t)M_DIM*KB_I];

// ---- helpers ----
__device__ __forceinline__ float fp8_to_f32(unsigned char b){
    __half_raw hr = __nv_cvt_fp8_to_halfraw((__nv_fp8_storage_t)b, __NV_E4M3);
    return __half2float(*(__half*)&hr);
}
__device__ __forceinline__ bool fp8_rt(float v){
    if(!isfinite(v) || fabsf(v) > 448.0f) return false;
    __nv_fp8_storage_t b = __nv_cvt_float_to_fp8(v, __NV_SATFINITE, __NV_E4M3);
    return fp8_to_f32((unsigned char)b) == v;
}
__device__ __forceinline__ __nv_bfloat16 fq1(float v, float s){
    float d = __fdiv_rn(v, s);
    __nv_fp8_storage_t b = __nv_cvt_float_to_fp8(d, __NV_SATFINITE, __NV_E4M3);
    return __float2bfloat16(fp8_to_f32((unsigned char)b));
}
__device__ __forceinline__ float exp_precise(float x){
    float n = rintf(x * 1.4426950408889634f);
    float r = fmaf(n, -0.693359375f, x);
    r = fmaf(n, 2.12194440e-4f, r);
    float p = 1.9841269841e-4f;
    p = fmaf(p, r, 1.3888888888e-3f);
    p = fmaf(p, r, 8.3333333333e-3f);
    p = fmaf(p, r, 4.1666666667e-2f);
    p = fmaf(p, r, 1.6666666667e-1f);
    p = fmaf(p, r, 0.5f);
    p = fmaf(p, r, 1.0f);
    p = fmaf(p, r, 1.0f);
    return ldexpf(p, (int)n);
}
__device__ __forceinline__ float sigmoid_precise(float x){
    float ax = fminf(fabsf(x), 87.0f);
    float e = exp_precise(-ax);
    float den = 1.0f + e;
    return (x >= 0.0f) ? __fdiv_rn(1.0f, den) : __fdiv_rn(e, den);
}
__device__ __forceinline__ void cpasync16(void* s, const void* g){
    unsigned sa = (unsigned)__cvta_generic_to_shared(s);
    asm volatile("cp.async.cg.shared.global [%0], [%1], 16;\n" :: "r"(sa), "l"(g));
}
__device__ __forceinline__ void mma16816(float* c, const unsigned* a, const unsigned* b){
    asm volatile("mma.sync.aligned.m16n8k16.row.col.f32.bf16.bf16.f32 "
        "{%0,%1,%2,%3}, {%4,%5,%6,%7}, {%8,%9}, {%0,%1,%2,%3};\n"
        : "+f"(c[0]), "+f"(c[1]), "+f"(c[2]), "+f"(c[3])
        : "r"(a[0]), "r"(a[1]), "r"(a[2]), "r"(a[3]), "r"(b[0]), "r"(b[1]));
}

// ---- format detection ----
__global__ void k_detect(const void* __restrict__ w){
    int tid = threadIdx.x;
    int ok32 = 1, ok16 = 1;
    for(int i = tid; i < 2048; i += blockDim.x){
        ok32 = ok32 && fp8_rt(((const float*)w)[i]);
        ok16 = ok16 && fp8_rt(__bfloat162float(((const __nv_bfloat16*)w)[i]));
    }
    int a32 = __syncthreads_and(ok32);
    int a16 = __syncthreads_and(ok16);
    if(tid == 0) g_fmt = a32 ? 1 : (a16 ? 2 : 0);
}

// ---- weight convert -> bf16 (exact) ----
__global__ void k_convert(const void* __restrict__ src, __nv_bfloat16* __restrict__ dst, size_t n){
    int fmt = g_fmt;
    size_t i = (size_t)blockIdx.x*blockDim.x + threadIdx.x;
    size_t stride = (size_t)gridDim.x*blockDim.x;
    size_t n4 = n >> 2;
    if(fmt == 1){
        const float4* s = (const float4*)src;
        for(size_t j = i; j < n4; j += stride){
            float4 v = s[j];
            union{ __nv_bfloat16 h[4]; uint2 u; } o;
            o.h[0]=__float2bfloat16(v.x); o.h[1]=__float2bfloat16(v.y);
            o.h[2]=__float2bfloat16(v.z); o.h[3]=__float2bfloat16(v.w);
            ((uint2*)dst)[j] = o.u;
        }
    } else if(fmt == 2){
        const uint2* s = (const uint2*)src;
        for(size_t j = i; j < n4; j += stride) ((uint2*)dst)[j] = s[j];
    } else {
        const uchar4* s = (const uchar4*)src;
        for(size_t j = i; j < n4; j += stride){
            uchar4 v = s[j];
            union{ __nv_bfloat16 h[4]; uint2 u; } o;
            o.h[0]=__float2bfloat16(fp8_to_f32(v.x));
            o.h[1]=__float2bfloat16(fp8_to_f32(v.y));
            o.h[2]=__float2bfloat16(fp8_to_f32(v.z));
            o.h[3]=__float2bfloat16(fp8_to_f32(v.w));
            ((uint2*)dst)[j] = o.u;
        }
    }
}

// ---- activation fake-quant (one warp per 128-group) ----
__global__ void k_quant_x(const float* __restrict__ x, __nv_bfloat16* __restrict__ xq,
                          float* __restrict__ xs){
    int gidx = (int)(((size_t)blockIdx.x*blockDim.x + threadIdx.x) >> 5);
    int lane = threadIdx.x & 31;
    if(gidx >= M_DIM*KB_H) return;
    int row = gidx / KB_H, g = gidx % KB_H;
    float4 v = ((const float4*)(x + (size_t)row*H_DIM + g*128))[lane];
    float am = fmaxf(fmaxf(fabsf(v.x),fabsf(v.y)), fmaxf(fabsf(v.z),fabsf(v.w)));
#pragma unroll
    for(int o = 16; o; o >>= 1) am = fmaxf(am, __shfl_xor_sync(0xffffffffu, am, o));
    float s = fmaxf(__fdiv_rn(am, 448.0f), 1e-12f);
    union{ __nv_bfloat16 h[4]; uint2 u; } o;
    o.h[0]=fq1(v.x,s); o.h[1]=fq1(v.y,s); o.h[2]=fq1(v.z,s); o.h[3]=fq1(v.w,s);
    ((uint2*)(xq + (size_t)row*H_DIM + g*128))[lane] = o.u;
    if(lane == 0) xs[(size_t)row*KB_H + g] = s;
}

// ---- SwiGLU + fake-quant of hidden ----
__global__ void k_swiglu(const float* __restrict__ gate, const float* __restrict__ up,
                         __nv_bfloat16* __restrict__ hq, float* __restrict__ hs){
    int gidx = (int)(((size_t)blockIdx.x*blockDim.x + threadIdx.x) >> 5);
    int lane = threadIdx.x & 31;
    if(gidx >= M_DIM*KB_I) return;
    int row = gidx / KB_I, g = gidx % KB_I;
    size_t base = (size_t)row*I_DIM + g*128;
    float4 gv = ((const float4*)(gate + base))[lane];
    float4 uv = ((const float4*)(up + base))[lane];
    float4 v;
    v.x = gv.x * sigmoid_precise(gv.x) * uv.x;
    v.y = gv.y * sigmoid_precise(gv.y) * uv.y;
    v.z = gv.z * sigmoid_precise(gv.z) * uv.z;
    v.w = gv.w * sigmoid_precise(gv.w) * uv.w;
    float am = fmaxf(fmaxf(fabsf(v.x),fabsf(v.y)), fmaxf(fabsf(v.z),fabsf(v.w)));
#pragma unroll
    for(int o = 16; o; o >>= 1) am = fmaxf(am, __shfl_xor_sync(0xffffffffu, am, o));
    float s = fmaxf(__fdiv_rn(am, 448.0f), 1e-12f);
    union{ __nv_bfloat16 h[4]; uint2 u; } o;
    o.h[0]=fq1(v.x,s); o.h[1]=fq1(v.y,s); o.h[2]=fq1(v.z,s); o.h[3]=fq1(v.w,s);
    ((uint2*)(hq + base))[lane] = o.u;
    if(lane == 0) hs[(size_t)row*KB_I + g] = s;
}

// ---- block-scaled GEMM: out[M,N] = (Aq*As) @ (W*Ws)^T ----
// 128x128 CTA tile, 8 warps (4m x 2n), K chunks of 64 double-buffered,
// scales folded in fp32 every 128 K.
#define SMS 72   // smem row stride (halves), conflict-free for frag loads
__global__ void __launch_bounds__(256, 1)
k_gemm(const __nv_bfloat16* __restrict__ Aq, const float* __restrict__ As,
       const __nv_bfloat16* __restrict__ W,  const float* __restrict__ Ws,
       float* __restrict__ out, int M, int N, int K){
    extern __shared__ __nv_bfloat16 smem[];
    __nv_bfloat16* sA = smem;                 // [2][128*SMS]
    __nv_bfloat16* sB = smem + 2*128*SMS;     // [2][128*SMS]
    const int tid = threadIdx.x;
    const int wid = tid >> 5, lane = tid & 31;
    const int q = lane >> 2, r = lane & 3;
    const int wm = wid & 3, wn = wid >> 2;    // warp tile 32(m) x 64(n)
    const int m0 = blockIdx.y*128, n0 = blockIdx.x*128;
    const int KS = K >> 7;                    // K/128 scale blocks
    const int NK = K >> 6;                    // chunks of 64

    float acc[2][8][4], part[2][8][4];
#pragma unroll
    for(int a=0;a<2;a++)
#pragma unroll
        for(int b=0;b<8;b++)
#pragma unroll
            for(int c=0;c<4;c++){ acc[a][b][c]=0.f; part[a][b][c]=0.f; }

    // prefetch chunk 0
    {
        const __nv_bfloat16* ga = Aq + (size_t)m0*K;
        const __nv_bfloat16* gb = W  + (size_t)n0*K;
#pragma unroll
        for(int i=0;i<4;i++){
            int idx = tid + i*256, row = idx>>3, c8 = idx&7;
            cpasync16(sA + row*SMS + c8*8, ga + (size_t)row*K + c8*8);
            cpasync16(sB + row*SMS + c8*8, gb + (size_t)row*K + c8*8);
        }
        asm volatile("cp.async.commit_group;\n");
    }

    for(int kc = 0; kc < NK; kc++){
        int buf = kc & 1;
        asm volatile("cp.async.wait_group 0;\n");
        __syncthreads();
        if(kc + 1 < NK){
            int nb = buf ^ 1;
            const __nv_bfloat16* ga = Aq + (size_t)m0*K + (kc+1)*64;
            const __nv_bfloat16* gb = W  + (size_t)n0*K + (kc+1)*64;
#pragma unroll
            for(int i=0;i<4;i++){
                int idx = tid + i*256, row = idx>>3, c8 = idx&7;
                cpasync16(sA + nb*128*SMS + row*SMS + c8*8, ga + (size_t)row*K + c8*8);
                cpasync16(sB + nb*128*SMS + row*SMS + c8*8, gb + (size_t)row*K + c8*8);
            }
            asm volatile("cp.async.commit_group;\n");
        }
        const __nv_bfloat16* bA = sA + buf*128*SMS;
        const __nv_bfloat16* bB = sB + buf*128*SMS;
#pragma unroll
        for(int ks = 0; ks < 4; ks++){
            int ko = ks*16;
            unsigned a[2][4], b[8][2];
#pragma unroll
            for(int mi=0;mi<2;mi++){
                const __nv_bfloat16* ap = bA + (wm*32 + mi*16 + q)*SMS + ko + r*2;
                a[mi][0] = *(const unsigned*)ap;
                a[mi][1] = *(const unsigned*)(ap + 8*SMS);
                a[mi][2] = *(const unsigned*)(ap + 8);
                a[mi][3] = *(const unsigned*)(ap + 8*SMS + 8);
            }
#pragma unroll
            for(int ni=0;ni<8;ni++){
                const __nv_bfloat16* bp = bB + (wn*64 + ni*8 + q)*SMS + ko + r*2;
                b[ni][0] = *(const unsigned*)bp;
                b[ni][1] = *(const unsigned*)(bp + 8);
            }
#pragma unroll
            for(int mi=0;mi<2;mi++)
#pragma unroll
                for(int ni=0;ni<8;ni++)
                    mma16816(part[mi][ni], a[mi], b[ni]);
        }
        if(kc & 1){
            int kb = kc >> 1;
            float sw = Ws[(size_t)blockIdx.x*KS + kb];
#pragma unroll
            for(int mi=0;mi<2;mi++){
                int r0 = m0 + wm*32 + mi*16 + q;
                float s0 = As[(size_t)r0*KS + kb] * sw;
                float s1 = As[(size_t)(r0+8)*KS + kb] * sw;
#pragma unroll
                for(int ni=0;ni<8;ni++){
                    acc[mi][ni][0] = fmaf(part[mi][ni][0], s0, acc[mi][ni][0]);
                    acc[mi][ni][1] = fmaf(part[mi][ni][1], s0, acc[mi][ni][1]);
                    acc[mi][ni][2] = fmaf(part[mi][ni][2], s1, acc[mi][ni][2]);
                    acc[mi][ni][3] = fmaf(part[mi][ni][3], s1, acc[mi][ni][3]);
                    part[mi][ni][0]=0.f; part[mi][ni][1]=0.f;
                    part[mi][ni][2]=0.f; part[mi][ni][3]=0.f;
                }
            }
        }
        __syncthreads();
    }
    // epilogue
#pragma unroll
    for(int mi=0;mi<2;mi++){
        int r0 = m0 + wm*32 + mi*16 + q;
#pragma unroll
        for(int ni=0;ni<8;ni++){
            int c = n0 + wn*64 + ni*8 + r*2;
            *(float2*)(out + (size_t)r0*N + c)     = make_float2(acc[mi][ni][0], acc[mi][ni][1]);
            *(float2*)(out + (size_t)(r0+8)*N + c) = make_float2(acc[mi][ni][2], acc[mi][ni][3]);
        }
    }
}

extern "C" void kernel_launch(void* const* d_in, const int* in_sizes, int n_in,
                              void* d_out, int out_size){
    const float* x = (const float*)d_in[0];
    const void*  wg = d_in[1]; const float* wgs = (const float*)d_in[2];
    const void*  wu = d_in[3]; const float* wus = (const float*)d_in[4];
    const void*  wd = d_in[5]; const float* wds = (const float*)d_in[6];
    float* out = (float*)d_out;

    __nv_bfloat16 *p_wg, *p_wu, *p_wd, *p_xq, *p_hq;
    float *p_xs, *p_gate, *p_up, *p_hs;
    cudaGetSymbolAddress((void**)&p_wg, g_wg);
    cudaGetSymbolAddress((void**)&p_wu, g_wu);
    cudaGetSymbolAddress((void**)&p_wd, g_wd);
    cudaGetSymbolAddress((void**)&p_xq, g_xq);
    cudaGetSymbolAddress((void**)&p_xs, g_xs);
    cudaGetSymbolAddress((void**)&p_gate, g_gate);
    cudaGetSymbolAddress((void**)&p_up, g_up);
    cudaGetSymbolAddress((void**)&p_hq, g_hq);
    cudaGetSymbolAddress((void**)&p_hs, g_hs);

    static bool attr_set = false;
    if(!attr_set){
        cudaFuncSetAttribute(k_gemm, cudaFuncAttributeMaxDynamicSharedMemorySize, 2*2*128*SMS*2);
        attr_set = true;
    }
    const int smem_sz = 2*2*128*SMS*2; // 73728 B

    k_detect<<<1, 256>>>(wg);
    k_convert<<<4096, 256>>>(wg, p_wg, (size_t)I_DIM*H_DIM);
    k_convert<<<4096, 256>>>(wu, p_wu, (size_t)I_DIM*H_DIM);
    k_convert<<<4096, 256>>>(wd, p_wd, (size_t)H_DIM*I_DIM);

    k_quant_x<<<(M_DIM*KB_H)/8, 256>>>(x, p_xq, p_xs);

    dim3 gGU(I_DIM/128, M_DIM/128);
    k_gemm<<<gGU, 256, smem_sz>>>(p_xq, p_xs, p_wg, wgs, p_gate, M_DIM, I_DIM, H_DIM);
    k_gemm<<<gGU, 256, smem_sz>>>(p_xq, p_xs, p_wu, wus, p_up,   M_DIM, I_DIM, H_DIM);

    k_swiglu<<<(M_DIM*KB_I)/8, 256>>>(p_gate, p_up, p_hq, p_hs);

    dim3 gD(H_DIM/128, M_DIM/128);
    k_gemm<<<gD, 256, smem_sz>>>(p_hq, p_hs, p_wd, wds, out, M_DIM, H_DIM, I_DIM);
}